// round 2
// baseline (speedup 1.0000x reference)
#include <cuda_runtime.h>
#include <math.h>

#define BATCH  8
#define CINCH  256
#define HIDCH  256
#define NHEADS 8
#define HDIM   32
#define KSZ    31
#define PADW   15
#define WIDTH  16384

// ---- scratch (device globals; no allocation allowed) ----
__device__ float g_qWk[CINCH * NHEADS];                 // [D][h]
__device__ float g_qb[NHEADS];
__device__ float g_costE[BATCH * NHEADS * WIDTH];       // 4 MB
__device__ float g_vc[BATCH * HIDCH * WIDTH];           // 128 MB
__device__ float g_r [BATCH * HIDCH * WIDTH];           // 128 MB

// ============================================================
// Kernel 0: precompute qWk[D][h], qb[h]  (batch-independent)
// ============================================================
__global__ void precompute_kernel(const float* __restrict__ query,
                                  const float* __restrict__ Wk,
                                  const float* __restrict__ Wkb) {
    __shared__ float sq[CINCH];
    __shared__ float qn[CINCH];
    __shared__ float nrm[NHEADS];
    int tid = threadIdx.x;   // 0..255
    float qv = query[tid];
    sq[tid] = qv * qv;
    __syncthreads();
    if (tid < NHEADS) {
        float s = 0.f;
        #pragma unroll
        for (int d = 0; d < HDIM; d++) s += sq[tid * HDIM + d];
        nrm[tid] = sqrtf(s) + 1e-6f;
    }
    __syncthreads();
    // q / (norm+eps) / sqrt(HD)
    qn[tid] = qv / nrm[tid / HDIM] * 0.17677669529663687f;
    __syncthreads();
    // qWk[D][h] = sum_d qn[h*32+d] * Wk[D*256 + h*32 + d]   (Wk is [CIN,HID])
    int D = tid;
    #pragma unroll
    for (int h = 0; h < NHEADS; h++) {
        float s = 0.f;
        const float* wrow = Wk + D * HIDCH + h * HDIM;
        #pragma unroll
        for (int d = 0; d < HDIM; d++) s += qn[h * HDIM + d] * wrow[d];
        g_qWk[D * NHEADS + h] = s;
    }
    if (tid < NHEADS) {
        float s = 0.f;
        #pragma unroll
        for (int d = 0; d < HDIM; d++) s += Wkb[tid * HDIM + d] * qn[tid * HDIM + d];
        g_qb[tid] = s;
    }
}

// ============================================================
// Kernel 1: cost_exp[b][h][w] = exp( sum_D x[b][D][w]*qWk[D][h] + qb[h] )
// ============================================================
__global__ void __launch_bounds__(256) cost_kernel(const float* __restrict__ x) {
    __shared__ float sW[CINCH * NHEADS];
    __shared__ float sb[NHEADS];
    int tid = threadIdx.x;
    for (int i = tid; i < CINCH * NHEADS; i += 256) sW[i] = g_qWk[i];
    if (tid < NHEADS) sb[tid] = g_qb[tid];
    __syncthreads();

    int b = blockIdx.y;
    int w = blockIdx.x * 256 + tid;
    const float* xb = x + (size_t)b * CINCH * WIDTH + w;

    float acc[NHEADS];
    #pragma unroll
    for (int h = 0; h < NHEADS; h++) acc[h] = sb[h];

    for (int D = 0; D < CINCH; D++) {
        float v = __ldg(xb + (size_t)D * WIDTH);
        #pragma unroll
        for (int h = 0; h < NHEADS; h++) acc[h] = fmaf(v, sW[D * NHEADS + h], acc[h]);
    }
    #pragma unroll
    for (int h = 0; h < NHEADS; h++)
        g_costE[((size_t)b * NHEADS + h) * WIDTH + w] = expf(acc[h]);
}

// ============================================================
// SGEMM: C[c][w] = sum_d Wt[c][d] * X[d][w]  (+ epilogue)
//   MODE 0: X = x (batch slice), Out = g_vc, scaled by cost_exp
//   MODE 1: X = g_r (batch slice), Out = out param, plain bias
// Tiles: BM=128, BN=128, BK=16, 256 threads, 8x8 microtile
// ============================================================
#define BM 128
#define BN 128
#define BK 16

template <int MODE>
__global__ void __launch_bounds__(256) gemm_kernel(const float* __restrict__ Wt,
                                                   const float* __restrict__ Xglobal,
                                                   const float* __restrict__ bias,
                                                   float* __restrict__ OutGlobal) {
    __shared__ __align__(16) float As[BK][BM];   // weight tile, transposed
    __shared__ __align__(16) float Bs[BK][BN];

    const int bn = blockIdx.x * BN;
    const int bm = blockIdx.y * BM;
    const int b  = blockIdx.z;

    const float* Xb = (MODE == 0)
        ? (Xglobal + (size_t)b * CINCH * WIDTH)
        : (g_r + (size_t)b * HIDCH * WIDTH);

    const int tid = threadIdx.x;
    const int tx = tid & 15;   // 0..15 (w dir)
    const int ty = tid >> 4;   // 0..15 (c dir)

    float acc[8][8];
    #pragma unroll
    for (int i = 0; i < 8; i++)
        #pragma unroll
        for (int j = 0; j < 8; j++) acc[i][j] = 0.f;

    for (int k0 = 0; k0 < CINCH; k0 += BK) {
        // load weight tile [BM x BK] -> As[k][m]  (512 float4 units)
        #pragma unroll
        for (int v = 0; v < 2; v++) {
            int u  = tid * 2 + v;
            int r  = u >> 2;       // 0..127 output channel row
            int c4 = u & 3;        // float4 idx within 16 cols
            float4 a4 = *(const float4*)(Wt + (size_t)(bm + r) * CINCH + k0 + c4 * 4);
            As[c4 * 4 + 0][r] = a4.x;
            As[c4 * 4 + 1][r] = a4.y;
            As[c4 * 4 + 2][r] = a4.z;
            As[c4 * 4 + 3][r] = a4.w;
        }
        // load X tile [BK x BN]
        #pragma unroll
        for (int v = 0; v < 2; v++) {
            int u  = tid * 2 + v;
            int r  = u >> 5;       // 0..15 (k row)
            int c4 = u & 31;       // float4 idx within 128 cols
            *(float4*)&Bs[r][c4 * 4] =
                *(const float4*)(Xb + (size_t)(k0 + r) * WIDTH + bn + c4 * 4);
        }
        __syncthreads();

        #pragma unroll
        for (int kk = 0; kk < BK; kk++) {
            float a[8], bb[8];
            *(float4*)&a[0]  = *(const float4*)&As[kk][ty * 8];
            *(float4*)&a[4]  = *(const float4*)&As[kk][ty * 8 + 4];
            *(float4*)&bb[0] = *(const float4*)&Bs[kk][tx * 8];
            *(float4*)&bb[4] = *(const float4*)&Bs[kk][tx * 8 + 4];
            #pragma unroll
            for (int i = 0; i < 8; i++)
                #pragma unroll
                for (int j = 0; j < 8; j++)
                    acc[i][j] = fmaf(a[i], bb[j], acc[i][j]);
        }
        __syncthreads();
    }

    // epilogue
    #pragma unroll
    for (int i = 0; i < 8; i++) {
        int c = bm + ty * 8 + i;
        float bv = bias[c];
        size_t obase = ((size_t)b * HIDCH + c) * WIDTH + bn + tx * 8;
        if (MODE == 0) {
            const float* ce = g_costE + ((size_t)b * NHEADS + (c >> 5)) * WIDTH + bn + tx * 8;
            float o[8];
            #pragma unroll
            for (int j = 0; j < 8; j++) o[j] = ce[j] * (acc[i][j] + bv);
            *(float4*)&g_vc[obase]     = *(float4*)&o[0];
            *(float4*)&g_vc[obase + 4] = *(float4*)&o[4];
        } else {
            float o[8];
            #pragma unroll
            for (int j = 0; j < 8; j++) o[j] = acc[i][j] + bv;
            *(float4*)&OutGlobal[obase]     = *(float4*)&o[0];
            *(float4*)&OutGlobal[obase + 4] = *(float4*)&o[4];
        }
    }
}

// ============================================================
// Kernel 3: 31-tap depthwise conv on vc and cost_exp, then ratio
//   r[b][c][w] = (sum_k vc[b][c][w-15+k]*rpeE[h][k]) /
//                (sum_k cE[b][h][w-15+k]*rpeE[h][k])
// ============================================================
__global__ void __launch_bounds__(256) conv_kernel(const float* __restrict__ rpe) {
    __shared__ float rk[KSZ];
    int c = blockIdx.y;
    int h = c >> 5;
    int b = blockIdx.z;
    if (threadIdx.x < KSZ) rk[threadIdx.x] = expf(rpe[h * KSZ + threadIdx.x]);
    __syncthreads();

    int w = blockIdx.x * 256 + threadIdx.x;
    const float* vrow = g_vc + ((size_t)b * HIDCH + c) * WIDTH;
    const float* crow = g_costE + ((size_t)b * NHEADS + h) * WIDTH;

    float sv = 0.f, sc = 0.f;
    int k0 = (w < PADW) ? (PADW - w) : 0;
    int k1 = (w + PADW >= WIDTH) ? (WIDTH + PADW - w) : KSZ;
    for (int k = k0; k < k1; k++) {
        float r = rk[k];
        int ww = w - PADW + k;
        sv = fmaf(__ldg(vrow + ww), r, sv);
        sc = fmaf(__ldg(crow + ww), r, sc);
    }
    g_r[((size_t)b * HIDCH + c) * WIDTH + w] = sv / sc;
}

// ============================================================
extern "C" void kernel_launch(void* const* d_in, const int* in_sizes, int n_in,
                              void* d_out, int out_size) {
    const float* x     = (const float*)d_in[0];
    const float* query = (const float*)d_in[1];
    const float* Wk    = (const float*)d_in[2];
    const float* Wkb   = (const float*)d_in[3];
    const float* rpe   = (const float*)d_in[4];
    const float* Wv    = (const float*)d_in[5];
    const float* bv    = (const float*)d_in[6];
    const float* Wo    = (const float*)d_in[7];
    const float* bo    = (const float*)d_in[8];
    float* out = (float*)d_out;

    precompute_kernel<<<1, 256>>>(query, Wk, Wkb);
    cost_kernel<<<dim3(WIDTH / 256, BATCH), 256>>>(x);
    gemm_kernel<0><<<dim3(WIDTH / BN, HIDCH / BM, BATCH), 256>>>(Wv, x, bv, nullptr);
    conv_kernel<<<dim3(WIDTH / 256, HIDCH, BATCH), 256>>>(rpe);
    gemm_kernel<1><<<dim3(WIDTH / BN, HIDCH / BM, BATCH), 256>>>(Wo, nullptr, bo, out);
}

// round 3
// speedup vs baseline: 1.4717x; 1.4717x over previous
#include <cuda_runtime.h>
#include <math.h>

#define BATCH  8
#define CINCH  256
#define HIDCH  256
#define NHEADS 8
#define HDIM   32
#define KSZ    31
#define PADW   15
#define WIDTH  16384

// ---- scratch (device globals; no allocation allowed) ----
__device__ float g_qWk[CINCH * NHEADS];                 // [D][h]
__device__ float g_qb[NHEADS];
__device__ float g_costE[BATCH * NHEADS * WIDTH];       // 4 MB
__device__ float g_rinv [BATCH * NHEADS * WIDTH];       // 4 MB  (1 / denom conv)
__device__ float g_vc[BATCH * HIDCH * WIDTH];           // 128 MB
__device__ float g_r [BATCH * HIDCH * WIDTH];           // 128 MB

// ============================================================
// Kernel 0: precompute qWk[D][h], qb[h]  (batch-independent)
// ============================================================
__global__ void precompute_kernel(const float* __restrict__ query,
                                  const float* __restrict__ Wk,
                                  const float* __restrict__ Wkb) {
    __shared__ float sq[CINCH];
    __shared__ float qn[CINCH];
    __shared__ float nrm[NHEADS];
    int tid = threadIdx.x;   // 0..255
    float qv = query[tid];
    sq[tid] = qv * qv;
    __syncthreads();
    if (tid < NHEADS) {
        float s = 0.f;
        #pragma unroll
        for (int d = 0; d < HDIM; d++) s += sq[tid * HDIM + d];
        nrm[tid] = sqrtf(s) + 1e-6f;
    }
    __syncthreads();
    qn[tid] = qv / nrm[tid / HDIM] * 0.17677669529663687f;   // /(norm+eps)/sqrt(HD)
    __syncthreads();
    int D = tid;
    #pragma unroll
    for (int h = 0; h < NHEADS; h++) {
        float s = 0.f;
        const float* wrow = Wk + D * HIDCH + h * HDIM;
        #pragma unroll
        for (int d = 0; d < HDIM; d++) s += qn[h * HDIM + d] * wrow[d];
        g_qWk[D * NHEADS + h] = s;
    }
    if (tid < NHEADS) {
        float s = 0.f;
        #pragma unroll
        for (int d = 0; d < HDIM; d++) s += Wkb[tid * HDIM + d] * qn[tid * HDIM + d];
        g_qb[tid] = s;
    }
}

// ============================================================
// Kernel 1: cost_exp[b][h][w] = exp( sum_D x[b][D][w]*qWk[D][h] + qb[h] )
// ============================================================
__global__ void __launch_bounds__(256) cost_kernel(const float* __restrict__ x) {
    __shared__ float sW[CINCH * NHEADS];
    __shared__ float sb[NHEADS];
    int tid = threadIdx.x;
    for (int i = tid; i < CINCH * NHEADS; i += 256) sW[i] = g_qWk[i];
    if (tid < NHEADS) sb[tid] = g_qb[tid];
    __syncthreads();

    int b = blockIdx.y;
    int w = blockIdx.x * 256 + tid;
    const float* xb = x + (size_t)b * CINCH * WIDTH + w;

    float acc[NHEADS];
    #pragma unroll
    for (int h = 0; h < NHEADS; h++) acc[h] = sb[h];

    for (int D = 0; D < CINCH; D++) {
        float v = __ldg(xb + (size_t)D * WIDTH);
        #pragma unroll
        for (int h = 0; h < NHEADS; h++) acc[h] = fmaf(v, sW[D * NHEADS + h], acc[h]);
    }
    #pragma unroll
    for (int h = 0; h < NHEADS; h++)
        g_costE[((size_t)b * NHEADS + h) * WIDTH + w] = expf(acc[h]);
}

// ============================================================
// Kernel 2: denominator conv (per b,h row):
//   rinv[b][h][w] = 1 / sum_k cE[b][h][w-15+k] * rpeE[h][k]
// ============================================================
__global__ void __launch_bounds__(256) denom_kernel(const float* __restrict__ rpe) {
    __shared__ float s[256 + 32];
    __shared__ float rks[KSZ];
    int h = blockIdx.y;
    int b = blockIdx.z;
    int w0 = blockIdx.x * 256;
    int tid = threadIdx.x;
    if (tid < KSZ) rks[tid] = expf(rpe[h * KSZ + tid]);
    const float* crow = g_costE + ((size_t)b * NHEADS + h) * WIDTH;
    #pragma unroll
    for (int i = tid; i < 256 + 32; i += 256) {
        int g = w0 - PADW + i;
        s[i] = (g >= 0 && g < WIDTH) ? crow[g] : 0.f;
    }
    __syncthreads();
    float rkr[KSZ];
    #pragma unroll
    for (int k = 0; k < KSZ; k++) rkr[k] = rks[k];
    float sc = 0.f;
    #pragma unroll
    for (int k = 0; k < KSZ; k++) sc = fmaf(s[tid + k], rkr[k], sc);
    g_rinv[((size_t)b * NHEADS + h) * WIDTH + w0 + tid] = 1.0f / sc;
}

// ============================================================
// Kernel 3: 31-tap depthwise conv on vc, times precomputed 1/denom.
//   Per block: one (b,c), 1024 outputs, ILP=4 per thread.
// ============================================================
#define CTILE 1024
__global__ void __launch_bounds__(256) conv_kernel(const float* __restrict__ rpe) {
    __shared__ __align__(16) float s[CTILE + 36];
    __shared__ float rks[KSZ];
    int c = blockIdx.y;
    int h = c >> 5;
    int b = blockIdx.z;
    int w0 = blockIdx.x * CTILE;
    int tid = threadIdx.x;
    if (tid < KSZ) rks[tid] = expf(rpe[h * KSZ + tid]);

    const float* vrow = g_vc + ((size_t)b * HIDCH + c) * WIDTH;
    // zero-padded tile load: s[i] = vrow[w0 - 15 + i]
    #pragma unroll
    for (int i = tid; i < CTILE + 36; i += 256) {
        int g = w0 - PADW + i;
        s[i] = (g >= 0 && g < WIDTH) ? __ldg(vrow + g) : 0.f;
    }
    __syncthreads();

    float rkr[KSZ];
    #pragma unroll
    for (int k = 0; k < KSZ; k++) rkr[k] = rks[k];

    const int t4 = tid * 4;
    float a0 = 0.f, a1 = 0.f, a2 = 0.f, a3 = 0.f;
    #pragma unroll
    for (int u = 0; u < 9; u++) {
        float4 v4 = *(const float4*)&s[t4 + u * 4];
        float vv[4] = {v4.x, v4.y, v4.z, v4.w};
        #pragma unroll
        for (int e = 0; e < 4; e++) {
            const int m = u * 4 + e;
            if (m >= 0 && m < KSZ)         a0 = fmaf(vv[e], rkr[m],     a0);
            if (m - 1 >= 0 && m - 1 < KSZ) a1 = fmaf(vv[e], rkr[m - 1], a1);
            if (m - 2 >= 0 && m - 2 < KSZ) a2 = fmaf(vv[e], rkr[m - 2], a2);
            if (m - 3 >= 0 && m - 3 < KSZ) a3 = fmaf(vv[e], rkr[m - 3], a3);
        }
    }
    const float* rinv = g_rinv + ((size_t)b * NHEADS + h) * WIDTH + w0 + t4;
    float4 ri = *(const float4*)rinv;
    float4 o;
    o.x = a0 * ri.x;
    o.y = a1 * ri.y;
    o.z = a2 * ri.z;
    o.w = a3 * ri.w;
    *(float4*)&g_r[((size_t)b * HIDCH + c) * WIDTH + w0 + t4] = o;
}

// ============================================================
// SGEMM: C[c][w] = sum_d Wt[c][d] * X[d][w]  (+ epilogue)
//   MODE 0: X = x (batch slice), Out = g_vc, scaled by cost_exp
//   MODE 1: X = g_r (batch slice), Out = out param, plain bias
// ============================================================
#define BM 128
#define BN 128
#define BK 16

template <int MODE>
__global__ void __launch_bounds__(256) gemm_kernel(const float* __restrict__ Wt,
                                                   const float* __restrict__ Xglobal,
                                                   const float* __restrict__ bias,
                                                   float* __restrict__ OutGlobal) {
    __shared__ __align__(16) float As[BK][BM];   // weight tile, transposed
    __shared__ __align__(16) float Bs[BK][BN];

    const int bn = blockIdx.x * BN;
    const int bm = blockIdx.y * BM;
    const int b  = blockIdx.z;

    const float* Xb = (MODE == 0)
        ? (Xglobal + (size_t)b * CINCH * WIDTH)
        : (g_r + (size_t)b * HIDCH * WIDTH);

    const int tid = threadIdx.x;
    const int tx = tid & 15;   // 0..15 (w dir)
    const int ty = tid >> 4;   // 0..15 (c dir)

    float acc[8][8];
    #pragma unroll
    for (int i = 0; i < 8; i++)
        #pragma unroll
        for (int j = 0; j < 8; j++) acc[i][j] = 0.f;

    for (int k0 = 0; k0 < CINCH; k0 += BK) {
        #pragma unroll
        for (int v = 0; v < 2; v++) {
            int u  = tid * 2 + v;
            int r  = u >> 2;
            int c4 = u & 3;
            float4 a4 = *(const float4*)(Wt + (size_t)(bm + r) * CINCH + k0 + c4 * 4);
            As[c4 * 4 + 0][r] = a4.x;
            As[c4 * 4 + 1][r] = a4.y;
            As[c4 * 4 + 2][r] = a4.z;
            As[c4 * 4 + 3][r] = a4.w;
        }
        #pragma unroll
        for (int v = 0; v < 2; v++) {
            int u  = tid * 2 + v;
            int r  = u >> 5;
            int c4 = u & 31;
            *(float4*)&Bs[r][c4 * 4] =
                *(const float4*)(Xb + (size_t)(k0 + r) * WIDTH + bn + c4 * 4);
        }
        __syncthreads();

        #pragma unroll
        for (int kk = 0; kk < BK; kk++) {
            float a[8], bb[8];
            *(float4*)&a[0]  = *(const float4*)&As[kk][ty * 8];
            *(float4*)&a[4]  = *(const float4*)&As[kk][ty * 8 + 4];
            *(float4*)&bb[0] = *(const float4*)&Bs[kk][tx * 8];
            *(float4*)&bb[4] = *(const float4*)&Bs[kk][tx * 8 + 4];
            #pragma unroll
            for (int i = 0; i < 8; i++)
                #pragma unroll
                for (int j = 0; j < 8; j++)
                    acc[i][j] = fmaf(a[i], bb[j], acc[i][j]);
        }
        __syncthreads();
    }

    #pragma unroll
    for (int i = 0; i < 8; i++) {
        int c = bm + ty * 8 + i;
        float bv = bias[c];
        size_t obase = ((size_t)b * HIDCH + c) * WIDTH + bn + tx * 8;
        if (MODE == 0) {
            const float* ce = g_costE + ((size_t)b * NHEADS + (c >> 5)) * WIDTH + bn + tx * 8;
            float o[8];
            #pragma unroll
            for (int j = 0; j < 8; j++) o[j] = ce[j] * (acc[i][j] + bv);
            *(float4*)&g_vc[obase]     = *(float4*)&o[0];
            *(float4*)&g_vc[obase + 4] = *(float4*)&o[4];
        } else {
            float o[8];
            #pragma unroll
            for (int j = 0; j < 8; j++) o[j] = acc[i][j] + bv;
            *(float4*)&OutGlobal[obase]     = *(float4*)&o[0];
            *(float4*)&OutGlobal[obase + 4] = *(float4*)&o[4];
        }
    }
}

// ============================================================
extern "C" void kernel_launch(void* const* d_in, const int* in_sizes, int n_in,
                              void* d_out, int out_size) {
    const float* x     = (const float*)d_in[0];
    const float* query = (const float*)d_in[1];
    const float* Wk    = (const float*)d_in[2];
    const float* Wkb   = (const float*)d_in[3];
    const float* rpe   = (const float*)d_in[4];
    const float* Wv    = (const float*)d_in[5];
    const float* bv    = (const float*)d_in[6];
    const float* Wo    = (const float*)d_in[7];
    const float* bo    = (const float*)d_in[8];
    float* out = (float*)d_out;

    precompute_kernel<<<1, 256>>>(query, Wk, Wkb);
    cost_kernel<<<dim3(WIDTH / 256, BATCH), 256>>>(x);
    denom_kernel<<<dim3(WIDTH / 256, NHEADS, BATCH), 256>>>(rpe);
    gemm_kernel<0><<<dim3(WIDTH / BN, HIDCH / BM, BATCH), 256>>>(Wv, x, bv, nullptr);
    conv_kernel<<<dim3(WIDTH / CTILE, HIDCH, BATCH), 256>>>(rpe);
    gemm_kernel<1><<<dim3(WIDTH / BN, HIDCH / BM, BATCH), 256>>>(Wo, nullptr, bo, out);
}